// round 11
// baseline (speedup 1.0000x reference)
#include <cuda_runtime.h>

#define T_STEPS 301
#define IN_DIM  40
#define H_DIM   64
#define G_DIM   256      // 4*H
#define KTOT    104      // IN + H
#define BTILE   32       // samples per CTA
#define NTHR    512      // 16 warps = 4 per SMSP
#define XST     36       // floats per operand row (32 samples + pad; 144 B, 16B-aligned)
#define TIN     (T_STEPS * IN_DIM)

// Shared memory layout (floats)
#define WQ_OFF   0
#define WQ_SIZE  (KTOT * G_DIM)          // 26624 : Wq[k][4*j+g]
#define XH_OFF   (WQ_OFF + WQ_SIZE)
#define XH_SIZE  (KTOT * XST)            // rows k<40: x_t, rows >=40: h_{t-1}
#define BIAS_OFF (XH_OFF + XH_SIZE)      // bq[4*j+g]
#define CLF_OFF  (BIAS_OFF + G_DIM)
#define SMEM_FLOATS (CLF_OFF + BTILE * 65)   // 32704 floats = 130816 B

typedef unsigned long long ull;

__device__ __forceinline__ ull pack2(float a, float b) {
    ull r; asm("mov.b64 %0, {%1,%2};" : "=l"(r) : "f"(a), "f"(b)); return r;
}
__device__ __forceinline__ void unpack2(ull v, float& a, float& b) {
    asm("mov.b64 {%0,%1}, %2;" : "=f"(a), "=f"(b) : "l"(v));
}
__device__ __forceinline__ void ffma2(ull& d, ull a, ull b) {
    asm("fma.rn.f32x2 %0, %1, %2, %0;" : "+l"(d) : "l"(a), "l"(b));
}
__device__ __forceinline__ float tanha(float x) {
    float y; asm("tanh.approx.f32 %0, %1;" : "=f"(y) : "f"(x)); return y;
}
__device__ __forceinline__ float sigm(float x) {
    return fmaf(0.5f, tanha(0.5f * x), 0.5f);
}

__global__ void __launch_bounds__(NTHR, 1)
lstm_fused_kernel(const float* __restrict__ x,
                  const float* __restrict__ w_ih,
                  const float* __restrict__ w_hh,
                  const float* __restrict__ b_ih,
                  const float* __restrict__ b_hh,
                  const float* __restrict__ w_clf,
                  const float* __restrict__ b_clf,
                  float* __restrict__ out)
{
    extern __shared__ float sm[];
    float* Wq    = sm + WQ_OFF;
    float* xhf   = sm + XH_OFF;
    float* bias  = sm + BIAS_OFF;
    float* shclf = sm + CLF_OFF;

    const int tid   = threadIdx.x;
    const int lane  = tid & 31;
    const int w     = tid >> 5;             // warp 0..15
    const int jblk  = w & 7;                // j block of 8
    const int shalf = w >> 3;               // sample half (16)
    const int j     = 8 * jblk + (lane >> 2);   // gate column 0..63
    const int sb    = 16 * shalf + 4 * (lane & 3); // first of 4 samples
    const int base  = blockIdx.x * BTILE;

    // ---- stage weights: Wq[k][4*j+g]  (warp's 8 j's -> 32 consecutive floats) ----
    for (int idx = tid; idx < WQ_SIZE; idx += NTHR) {
        int k = idx >> 8, r = idx & 255;
        int jj = r >> 2, g = r & 3;
        Wq[idx] = (k < IN_DIM) ? w_ih[(g * H_DIM + jj) * IN_DIM + k]
                               : w_hh[(g * H_DIM + jj) * H_DIM + (k - IN_DIM)];
    }
    if (tid < G_DIM) {
        int jj = tid >> 2, g = tid & 3;
        bias[tid] = b_ih[g * H_DIM + jj] + b_hh[g * H_DIM + jj];
    }
    // zero h rows (t=0 hidden state)
    for (int f = tid; f < H_DIM * BTILE; f += NTHR)
        xhf[(IN_DIM + (f >> 5)) * XST + (f & 31)] = 0.f;

    // ---- x staging: 1280 floats / 512 threads -> up to 3 each ----
    int xs[3], xk[3], xv[3];
    #pragma unroll
    for (int i = 0; i < 3; i++) {
        int f = tid + i * NTHR;
        xv[i] = (f < BTILE * IN_DIM);
        int ff = xv[i] ? f : 0;
        xs[i] = ff / IN_DIM;
        xk[i] = ff - xs[i] * IN_DIM;
    }
    const float* xbase = x + (size_t)base * TIN;

    float xr[3];
    #pragma unroll
    for (int i = 0; i < 3; i++)
        if (xv[i]) xr[i] = xbase[(size_t)xs[i] * TIN + xk[i]];   // x_0

    __syncthreads();   // weights + bias + h-zero visible

    // packed biases in registers (one float4 load)
    ull bp[4];
    {
        float4 bv = *(const float4*)(bias + 4 * j);
        bp[0] = pack2(bv.x, bv.x); bp[1] = pack2(bv.y, bv.y);
        bp[2] = pack2(bv.z, bv.z); bp[3] = pack2(bv.w, bv.w);
    }

    float c[4], clf[4];
    #pragma unroll
    for (int i = 0; i < 4; i++) { c[i] = 0.f; clf[i] = 0.f; }

    const float* wp = Wq + 4 * j;
    const float* xp = xhf + sb;

    for (int t = 0; t < T_STEPS; t++) {
        // stage x_t (x rows only; disjoint from h rows)
        #pragma unroll
        for (int i = 0; i < 3; i++)
            if (xv[i]) xhf[xk[i] * XST + xs[i]] = xr[i];
        // prefetch x_{t+1}
        if (t + 1 < T_STEPS) {
            #pragma unroll
            for (int i = 0; i < 3; i++)
                if (xv[i]) xr[i] = xbase[(size_t)xs[i] * TIN + (t + 1) * IN_DIM + xk[i]];
        }
        float wc = __ldg(&w_clf[t * H_DIM + j]);

        __syncthreads();   // x_t + h_{t-1} staged

        // ---- z = [x_t ; h_{t-1}] @ W^T : 104-deep, 8 f32x2 accumulators ----
        ull acc[4][2];
        #pragma unroll
        for (int g = 0; g < 4; g++) { acc[g][0] = bp[g]; acc[g][1] = bp[g]; }

        #pragma unroll 8
        for (int k = 0; k < KTOT; k++) {
            float4 wv = *(const float4*)(wp + k * G_DIM);        // 4 gate weights (1 phase/warp)
            ulonglong2 xv2 = *(const ulonglong2*)(xp + k * XST); // 4 samples (1 phase/warp)
            ull W0 = pack2(wv.x, wv.x), W1 = pack2(wv.y, wv.y);
            ull W2 = pack2(wv.z, wv.z), W3 = pack2(wv.w, wv.w);
            ffma2(acc[0][0], W0, xv2.x); ffma2(acc[0][1], W0, xv2.y);
            ffma2(acc[1][0], W1, xv2.x); ffma2(acc[1][1], W1, xv2.y);
            ffma2(acc[2][0], W2, xv2.x); ffma2(acc[2][1], W2, xv2.y);
            ffma2(acc[3][0], W3, xv2.x); ffma2(acc[3][1], W3, xv2.y);
        }

        __syncthreads();   // all GEMM reads of xhf done before h rows are overwritten

        // ---- gates: i,f,g,o all local for 4 samples ----
        float hv[4];
        #pragma unroll
        for (int p = 0; p < 2; p++) {
            float zi0, zi1, zf0, zf1, zg0, zg1, zo0, zo1;
            unpack2(acc[0][p], zi0, zi1);
            unpack2(acc[1][p], zf0, zf1);
            unpack2(acc[2][p], zg0, zg1);
            unpack2(acc[3][p], zo0, zo1);
            float cc0 = sigm(zf0) * c[2*p]   + sigm(zi0) * tanha(zg0);
            float cc1 = sigm(zf1) * c[2*p+1] + sigm(zi1) * tanha(zg1);
            c[2*p]   = cc0;  c[2*p+1] = cc1;
            hv[2*p]   = sigm(zo0) * tanha(cc0);
            hv[2*p+1] = sigm(zo1) * tanha(cc1);
            clf[2*p]   = fmaf(hv[2*p],   wc, clf[2*p]);
            clf[2*p+1] = fmaf(hv[2*p+1], wc, clf[2*p+1]);
        }
        // store h_t for this thread's (j, 4 samples): one STS.128
        *(float4*)(xhf + (IN_DIM + j) * XST + sb) =
            make_float4(hv[0], hv[1], hv[2], hv[3]);
    }

    // ---- classifier reduction over j ----
    __syncthreads();
    #pragma unroll
    for (int m = 0; m < 4; m++)
        shclf[(sb + m) * 65 + j] = clf[m];
    __syncthreads();
    if (tid < BTILE) {
        float s = b_clf[0];
        #pragma unroll 8
        for (int jj = 0; jj < H_DIM; jj++) s += shclf[tid * 65 + jj];
        out[base + tid] = s;
    }
}

extern "C" void kernel_launch(void* const* d_in, const int* in_sizes, int n_in,
                              void* d_out, int out_size)
{
    const float* x     = (const float*)d_in[0];
    const float* w_ih  = (const float*)d_in[1];
    const float* w_hh  = (const float*)d_in[2];
    const float* b_ih  = (const float*)d_in[3];
    const float* b_hh  = (const float*)d_in[4];
    const float* w_clf = (const float*)d_in[5];
    const float* b_clf = (const float*)d_in[6];
    float* out = (float*)d_out;

    const int B = in_sizes[0] / TIN;   // 4096
    const int smem_bytes = SMEM_FLOATS * sizeof(float);

    cudaFuncSetAttribute(lstm_fused_kernel,
                         cudaFuncAttributeMaxDynamicSharedMemorySize, smem_bytes);
    lstm_fused_kernel<<<B / BTILE, NTHR, smem_bytes>>>(
        x, w_ih, w_hh, b_ih, b_hh, w_clf, b_clf, out);
}

// round 13
// speedup vs baseline: 1.0011x; 1.0011x over previous
#include <cuda_runtime.h>

#define T_STEPS 301
#define IN_DIM  40
#define H_DIM   64
#define G_DIM   256      // 4*H
#define KTOT    104      // IN + H
#define BTILE   32       // sample slots per CTA (<=28 used)
#define NCTA    148
#define NTHR    512      // 16 warps = 4 per SMSP
#define XST     36       // floats per operand row (32 slots + pad; 144 B)
#define TIN     (T_STEPS * IN_DIM)

// Shared memory layout (floats)
#define WQ_OFF   0
#define WQ_SIZE  (KTOT * G_DIM)          // 26624 : Wq[k][4*j+g]
#define B0_OFF   (WQ_OFF + WQ_SIZE)      // operand buffer 0: [104][XST]
#define B1_OFF   (B0_OFF + KTOT * XST)   // operand buffer 1
#define BIAS_OFF (B1_OFF + KTOT * XST)
#define CLF_OFF  (BIAS_OFF + G_DIM)
#define SMEM_FLOATS (CLF_OFF + BTILE * 65)   // 36448 floats = 145792 B

typedef unsigned long long ull;

__device__ __forceinline__ ull pack2(float a, float b) {
    ull r; asm("mov.b64 %0, {%1,%2};" : "=l"(r) : "f"(a), "f"(b)); return r;
}
__device__ __forceinline__ void unpack2(ull v, float& a, float& b) {
    asm("mov.b64 {%0,%1}, %2;" : "=f"(a), "=f"(b) : "l"(v));
}
__device__ __forceinline__ void ffma2(ull& d, ull a, ull b) {
    asm("fma.rn.f32x2 %0, %1, %2, %0;" : "+l"(d) : "l"(a), "l"(b));
}
__device__ __forceinline__ float tanha(float x) {
    float y; asm("tanh.approx.f32 %0, %1;" : "=f"(y) : "f"(x)); return y;
}
__device__ __forceinline__ float sigm(float x) {
    return fmaf(0.5f, tanha(0.5f * x), 0.5f);
}

__global__ void __launch_bounds__(NTHR, 1)
lstm_fused_kernel(const float* __restrict__ x,
                  const float* __restrict__ w_ih,
                  const float* __restrict__ w_hh,
                  const float* __restrict__ b_ih,
                  const float* __restrict__ b_hh,
                  const float* __restrict__ w_clf,
                  const float* __restrict__ b_clf,
                  float* __restrict__ out)
{
    extern __shared__ float sm[];
    float* Wq    = sm + WQ_OFF;
    float* bias  = sm + BIAS_OFF;
    float* shclf = sm + CLF_OFF;

    const int tid   = threadIdx.x;
    const int lane  = tid & 31;
    const int w     = tid >> 5;
    const int j     = 8 * (w & 7) + (lane >> 2);       // gate column 0..63
    const int sb    = 16 * (w >> 3) + 4 * (lane & 3);  // first of 4 sample slots
    const int cid   = blockIdx.x;
    const int ofs   = (cid < 100) ? 28 * cid : 2800 + 27 * (cid - 100);
    const int cnt   = (cid < 100) ? 28 : 27;

    // ---- stage weights: Wq[k][4*j+g] ----
    for (int idx = tid; idx < WQ_SIZE; idx += NTHR) {
        int k = idx >> 8, r = idx & 255;
        int jj = r >> 2, g = r & 3;
        Wq[idx] = (k < IN_DIM) ? w_ih[(g * H_DIM + jj) * IN_DIM + k]
                               : w_hh[(g * H_DIM + jj) * H_DIM + (k - IN_DIM)];
    }
    if (tid < G_DIM) {
        int jj = tid >> 2, g = tid & 3;
        bias[tid] = b_ih[g * H_DIM + jj] + b_hh[g * H_DIM + jj];
    }
    // zero BOTH operand buffers (covers h_0 = 0 and padding columns)
    for (int f = tid; f < 2 * KTOT * XST; f += NTHR)
        sm[B0_OFF + f] = 0.f;

    // ---- x staging slots ----
    int xs[3], xk[3], xv[3];
    #pragma unroll
    for (int i = 0; i < 3; i++) {
        int f = tid + i * NTHR;
        int in_rng = (f < BTILE * IN_DIM);
        int ff = in_rng ? f : 0;
        xs[i] = ff / IN_DIM;
        xk[i] = ff - xs[i] * IN_DIM;
        xv[i] = in_rng && (xs[i] < cnt);   // only real samples
    }
    const float* xbase = x + (size_t)ofs * TIN;

    float xr[3];
    #pragma unroll
    for (int i = 0; i < 3; i++)
        if (xv[i]) xr[i] = xbase[(size_t)xs[i] * TIN + xk[i]];   // x_0

    __syncthreads();   // zeroing done before x_0 staged (different thread mapping)

    // stage x_0 into buf0
    #pragma unroll
    for (int i = 0; i < 3; i++)
        if (xv[i]) sm[B0_OFF + xk[i] * XST + xs[i]] = xr[i];
    // prefetch x_1
    #pragma unroll
    for (int i = 0; i < 3; i++)
        if (xv[i]) xr[i] = xbase[(size_t)xs[i] * TIN + IN_DIM + xk[i]];

    __syncthreads();   // weights + bias + buf0 visible

    ull bp[4];
    {
        float4 bv = *(const float4*)(bias + 4 * j);
        bp[0] = pack2(bv.x, bv.x); bp[1] = pack2(bv.y, bv.y);
        bp[2] = pack2(bv.z, bv.z); bp[3] = pack2(bv.w, bv.w);
    }

    float c[4], clf[4];
    #pragma unroll
    for (int i = 0; i < 4; i++) { c[i] = 0.f; clf[i] = 0.f; }

    const float* wp = Wq + 4 * j;
    const float* rb = sm + B0_OFF;   // read buffer
    float*       wb = sm + B1_OFF;   // write buffer

    for (int t = 0; t < T_STEPS; t++) {
        float wc = __ldg(&w_clf[t * H_DIM + j]);

        // ---- z = [x_t ; h_{t-1}] @ W^T from read buffer ----
        ull acc[4][2];
        #pragma unroll
        for (int g = 0; g < 4; g++) { acc[g][0] = bp[g]; acc[g][1] = bp[g]; }

        const float* xp = rb + sb;
        #pragma unroll 8
        for (int k = 0; k < KTOT; k++) {
            float4 wv = *(const float4*)(wp + k * G_DIM);
            ulonglong2 xv2 = *(const ulonglong2*)(xp + k * XST);
            ull W0 = pack2(wv.x, wv.x), W1 = pack2(wv.y, wv.y);
            ull W2 = pack2(wv.z, wv.z), W3 = pack2(wv.w, wv.w);
            ffma2(acc[0][0], W0, xv2.x); ffma2(acc[0][1], W0, xv2.y);
            ffma2(acc[1][0], W1, xv2.x); ffma2(acc[1][1], W1, xv2.y);
            ffma2(acc[2][0], W2, xv2.x); ffma2(acc[2][1], W2, xv2.y);
            ffma2(acc[3][0], W3, xv2.x); ffma2(acc[3][1], W3, xv2.y);
        }

        // ---- gates ----
        float hv[4];
        #pragma unroll
        for (int p = 0; p < 2; p++) {
            float zi0, zi1, zf0, zf1, zg0, zg1, zo0, zo1;
            unpack2(acc[0][p], zi0, zi1);
            unpack2(acc[1][p], zf0, zf1);
            unpack2(acc[2][p], zg0, zg1);
            unpack2(acc[3][p], zo0, zo1);
            float cc0 = sigm(zf0) * c[2*p]   + sigm(zi0) * tanha(zg0);
            float cc1 = sigm(zf1) * c[2*p+1] + sigm(zi1) * tanha(zg1);
            c[2*p]   = cc0;  c[2*p+1] = cc1;
            hv[2*p]   = sigm(zo0) * tanha(cc0);
            hv[2*p+1] = sigm(zo1) * tanha(cc1);
            clf[2*p]   = fmaf(hv[2*p],   wc, clf[2*p]);
            clf[2*p+1] = fmaf(hv[2*p+1], wc, clf[2*p+1]);
        }

        if (t < T_STEPS - 1) {
            // h_t into write buffer (one STS.128)
            *(float4*)(wb + (IN_DIM + j) * XST + sb) =
                make_float4(hv[0], hv[1], hv[2], hv[3]);
            // x_{t+1} into write buffer
            #pragma unroll
            for (int i = 0; i < 3; i++)
                if (xv[i]) wb[xk[i] * XST + xs[i]] = xr[i];
            // prefetch x_{t+2}
            if (t + 2 < T_STEPS) {
                #pragma unroll
                for (int i = 0; i < 3; i++)
                    if (xv[i]) xr[i] = xbase[(size_t)xs[i] * TIN + (t + 2) * IN_DIM + xk[i]];
            }
            __syncthreads();   // single barrier per step
            const float* tmp = rb; rb = wb; wb = (float*)tmp;
        }
    }

    // ---- classifier reduction over j ----
    #pragma unroll
    for (int m = 0; m < 4; m++)
        shclf[(sb + m) * 65 + j] = clf[m];
    __syncthreads();
    if (tid < cnt) {
        float s = b_clf[0];
        #pragma unroll 8
        for (int jj = 0; jj < H_DIM; jj++) s += shclf[tid * 65 + jj];
        out[ofs + tid] = s;
    }
}

extern "C" void kernel_launch(void* const* d_in, const int* in_sizes, int n_in,
                              void* d_out, int out_size)
{
    const float* x     = (const float*)d_in[0];
    const float* w_ih  = (const float*)d_in[1];
    const float* w_hh  = (const float*)d_in[2];
    const float* b_ih  = (const float*)d_in[3];
    const float* b_hh  = (const float*)d_in[4];
    const float* w_clf = (const float*)d_in[5];
    const float* b_clf = (const float*)d_in[6];
    float* out = (float*)d_out;

    const int smem_bytes = SMEM_FLOATS * sizeof(float);
    cudaFuncSetAttribute(lstm_fused_kernel,
                         cudaFuncAttributeMaxDynamicSharedMemorySize, smem_bytes);
    lstm_fused_kernel<<<NCTA, NTHR, smem_bytes>>>(
        x, w_ih, w_hh, b_ih, b_hh, w_clf, b_clf, out);
}

// round 16
// speedup vs baseline: 2.3974x; 2.3949x over previous
#include <cuda_runtime.h>
#include <cuda_bf16.h>
#include <cstdint>

#define T_STEPS 301
#define IN_DIM  40
#define H_DIM   64
#define NTHR    512
#define NCTA    148
#define TIN     (T_STEPS * IN_DIM)

// A/B rows are 120 bf16 = 240 bytes (112 used: 40 x + 64 h + 1 bias + pad)
#define AST 240
#define BST 240

// ---- shared memory byte offsets ----
#define OFF_CLF 0                      // 32*65*4 = 8320
#define OFF_Z   8320                   // 16 warps * 16*34*4 = 34816
#define OFF_B   43136                  // 4 bufs (ph0hi, ph0lo, ph1hi, ph1lo) * 7680
#define OFF_A   73856                  // Ahi [256][120]bf16 = 61440, then Alo
#define A_LO    61440
#define SMEM_BYTES 196736              // 192.1 KB

typedef unsigned int uint;

__device__ __forceinline__ uint smem_u32(const void* p) {
    uint a; asm("{ .reg .u64 t; cvta.to.shared.u64 t, %1; cvt.u32.u64 %0, t; }"
                : "=r"(a) : "l"(p));
    return a;
}
__device__ __forceinline__ float tanha(float x) {
    float y; asm("tanh.approx.f32 %0, %1;" : "=f"(y) : "f"(x)); return y;
}
__device__ __forceinline__ float sigm(float x) {
    return fmaf(0.5f, tanha(0.5f * x), 0.5f);
}
__device__ __forceinline__ void bsplit(float v, __nv_bfloat16& hi, __nv_bfloat16& lo) {
    hi = __float2bfloat16(v);
    lo = __float2bfloat16(v - __bfloat162float(hi));
}

#define LDSM4(r, addr) asm volatile( \
    "ldmatrix.sync.aligned.m8n8.x4.shared.b16 {%0,%1,%2,%3}, [%4];" \
    : "=r"((r)[0]), "=r"((r)[1]), "=r"((r)[2]), "=r"((r)[3]) : "r"(addr))

#define MMA(dv, av, b0v, b1v) asm volatile( \
    "mma.sync.aligned.m16n8k16.row.col.f32.bf16.bf16.f32 " \
    "{%0,%1,%2,%3}, {%4,%5,%6,%7}, {%8,%9}, {%0,%1,%2,%3};" \
    : "+f"((dv)[0]), "+f"((dv)[1]), "+f"((dv)[2]), "+f"((dv)[3]) \
    : "r"((av)[0]), "r"((av)[1]), "r"((av)[2]), "r"((av)[3]), \
      "r"(b0v), "r"(b1v))

__global__ void __launch_bounds__(NTHR, 1)
lstm_hmma_kernel(const float* __restrict__ x,
                 const float* __restrict__ w_ih,
                 const float* __restrict__ w_hh,
                 const float* __restrict__ b_ih,
                 const float* __restrict__ b_hh,
                 const float* __restrict__ w_clf,
                 const float* __restrict__ b_clf,
                 float* __restrict__ out)
{
    extern __shared__ char smem[];
    const uint sbase = smem_u32(smem);
    float* shclf = (float*)(smem + OFF_CLF);

    const int tid  = threadIdx.x;
    const int lane = tid & 31;
    const int w    = tid >> 5;          // warp 0..15: M-stripe rows 16w..16w+15
    const int gid  = lane >> 2;         // fragment row group
    const int tid4 = lane & 3;
    const int jloc = lane >> 3;         // 0..3
    const int nb   = lane & 7;
    const int jg   = 4 * w + jloc;      // global gate column j
    const int cid  = blockIdx.x;
    const int ofs  = (cid < 100) ? 28 * cid : 2800 + 27 * (cid - 100);
    const int cnt  = (cid < 100) ? 28 : 27;

    // ---- zero all 4 B operand buffers (h_0 = 0, padding) ----
    for (int i = tid; i < 4 * 7680 / 4; i += NTHR)
        ((uint*)(smem + OFF_B))[i] = 0;

    // ---- stage weights: A[row=4j+g][k] hi + lo, bias folded at k=104 ----
    for (int idx = tid; idx < 256 * 120; idx += NTHR) {
        int row = idx / 120, k = idx - row * 120;
        int j = row >> 2, g = row & 3;
        int gr = g * H_DIM + j;
        float v = 0.f;
        if (k < IN_DIM)                   v = w_ih[gr * IN_DIM + k];
        else if (k < IN_DIM + H_DIM)      v = w_hh[gr * H_DIM + (k - IN_DIM)];
        else if (k == 104)                v = b_ih[gr] + b_hh[gr];
        __nv_bfloat16 hi, lo; bsplit(v, hi, lo);
        *(__nv_bfloat16*)(smem + OFF_A + row * AST + k * 2)        = hi;
        *(__nv_bfloat16*)(smem + OFF_A + A_LO + row * AST + k * 2) = lo;
    }
    __syncthreads();   // zeroing + A staging complete

    // ---- bias row (k=104) of B-hi = 1.0 in BOTH phases ----
    if (tid < 32) {
        *(__nv_bfloat16*)(smem + OFF_B +          tid * BST + 208) = __float2bfloat16(1.0f);
        *(__nv_bfloat16*)(smem + OFF_B + 15360 +  tid * BST + 208) = __float2bfloat16(1.0f);
    }

    // ---- x staging slots (1280 elems / 512 thr -> up to 3) ----
    int xs[3], xk[3], xv[3];
    #pragma unroll
    for (int i = 0; i < 3; i++) {
        int f = tid + i * NTHR;
        int in_rng = (f < 32 * IN_DIM);
        int ff = in_rng ? f : 0;
        xs[i] = ff / IN_DIM;
        xk[i] = ff - xs[i] * IN_DIM;
        xv[i] = in_rng && (xs[i] < cnt);
    }
    const float* xbase = x + (size_t)ofs * TIN;

    // stage x_0 into phase-0 buffers (B is n-major: [n][k])
    #pragma unroll
    for (int i = 0; i < 3; i++) if (xv[i]) {
        __nv_bfloat16 hi, lo; bsplit(xbase[(size_t)xs[i] * TIN + xk[i]], hi, lo);
        *(__nv_bfloat16*)(smem + OFF_B +        xs[i] * BST + xk[i] * 2) = hi;
        *(__nv_bfloat16*)(smem + OFF_B + 7680 + xs[i] * BST + xk[i] * 2) = lo;
    }
    float xr[3];
    #pragma unroll
    for (int i = 0; i < 3; i++)
        if (xv[i]) xr[i] = xbase[(size_t)xs[i] * TIN + IN_DIM + xk[i]];   // x_1

    // ---- preload resident A-hi fragments (7 K-tiles) ----
    const uint aHiBase = sbase + OFF_A + (16 * w + (lane & 15)) * AST + (lane >> 4) * 16;
    const uint aLoBase = aHiBase + A_LO;
    uint aHi[7][4];
    #pragma unroll
    for (int kt = 0; kt < 7; kt++) LDSM4(aHi[kt], aHiBase + kt * 32);

    __syncthreads();   // bias + x_0 staged before first MMA

    // B ldmatrix per-lane offset: n-row + k-column component
    const uint bOff = ((lane & 7) + ((lane >> 4) & 1) * 8) * BST + ((lane >> 3) & 1) * 16;
    char* zW = smem + OFF_Z + w * 2176;   // warp-private z tile [16][34] f32

    float c[4]   = {0.f, 0.f, 0.f, 0.f};
    float clf[4] = {0.f, 0.f, 0.f, 0.f};

    for (int t = 0; t < T_STEPS; t++) {
        const int p = t & 1;
        const uint phR = (uint)(p * 15360);         // read-phase byte offset from OFF_B
        const uint phW = (uint)((p ^ 1) * 15360);   // write-phase byte offset
        const uint sBhi = sbase + OFF_B + phR;
        const uint sBlo = sBhi + 7680;

        float d[4][4];
        #pragma unroll
        for (int nt = 0; nt < 4; nt++)
            #pragma unroll
            for (int i = 0; i < 4; i++) d[nt][i] = 0.f;

        // ---- HMMA mainloop: 7 K-tiles x 4 N-tiles x 3 split terms ----
        #pragma unroll
        for (int kt = 0; kt < 7; kt++) {
            uint bh[8], bl[8], al[4];
            LDSM4(bh,     sBhi + bOff + kt * 32);            // n-tiles 0,1
            LDSM4(bh + 4, sBhi + bOff + 3840 + kt * 32);     // n-tiles 2,3
            LDSM4(bl,     sBlo + bOff + kt * 32);
            LDSM4(bl + 4, sBlo + bOff + 3840 + kt * 32);
            LDSM4(al,     aLoBase + kt * 32);                // streamed A-lo
            #pragma unroll
            for (int nt = 0; nt < 4; nt++) {
                uint b0h = bh[2 * nt], b1h = bh[2 * nt + 1];
                uint b0l = bl[2 * nt], b1l = bl[2 * nt + 1];
                MMA(d[nt], aHi[kt], b0h, b1h);   // Whi * Bhi
                MMA(d[nt], al,      b0h, b1h);   // Wlo * Bhi
                MMA(d[nt], aHi[kt], b0l, b1l);   // Whi * Blo
            }
        }

        // ---- z to warp-private smem tile ----
        #pragma unroll
        for (int nt = 0; nt < 4; nt++) {
            *(float2*)(zW + gid * 136 + (8 * nt + 2 * tid4) * 4)       = make_float2(d[nt][0], d[nt][1]);
            *(float2*)(zW + (gid + 8) * 136 + (8 * nt + 2 * tid4) * 4) = make_float2(d[nt][2], d[nt][3]);
        }
        __syncwarp();

        // ---- gates: thread owns (j = jg) x 4 samples (n = nb + 8m) ----
        float wc = __ldg(&w_clf[t * H_DIM + jg]);
        char* nHi = smem + OFF_B + phW;          // next-phase hi buffer
        char* nLo = nHi + 7680;
        #pragma unroll
        for (int m = 0; m < 4; m++) {
            int n = nb + 8 * m;
            float zi = *(float*)(zW + (4 * jloc + 0) * 136 + n * 4);
            float zf = *(float*)(zW + (4 * jloc + 1) * 136 + n * 4);
            float zg = *(float*)(zW + (4 * jloc + 2) * 136 + n * 4);
            float zo = *(float*)(zW + (4 * jloc + 3) * 136 + n * 4);
            float cc = sigm(zf) * c[m] + sigm(zi) * tanha(zg);
            c[m] = cc;
            float h = sigm(zo) * tanha(cc);
            clf[m] = fmaf(h, wc, clf[m]);
            if (t < T_STEPS - 1) {
                __nv_bfloat16 hi, lo; bsplit(h, hi, lo);
                *(__nv_bfloat16*)(nHi + n * BST + (IN_DIM + jg) * 2) = hi;
                *(__nv_bfloat16*)(nLo + n * BST + (IN_DIM + jg) * 2) = lo;
            }
        }

        if (t < T_STEPS - 1) {
            // stage x_{t+1} into next-phase buffers
            #pragma unroll
            for (int i = 0; i < 3; i++) if (xv[i]) {
                __nv_bfloat16 hi, lo; bsplit(xr[i], hi, lo);
                *(__nv_bfloat16*)(nHi + xs[i] * BST + xk[i] * 2) = hi;
                *(__nv_bfloat16*)(nLo + xs[i] * BST + xk[i] * 2) = lo;
            }
            if (t + 2 < T_STEPS) {
                #pragma unroll
                for (int i = 0; i < 3; i++)
                    if (xv[i]) xr[i] = xbase[(size_t)xs[i] * TIN + (t + 2) * IN_DIM + xk[i]];
            }
            __syncthreads();   // next-phase B published before next HMMA
        }
    }

    // ---- classifier reduction over j ----
    #pragma unroll
    for (int m = 0; m < 4; m++)
        shclf[(nb + 8 * m) * 65 + jg] = clf[m];
    __syncthreads();
    if (tid < cnt) {
        float s = b_clf[0];
        #pragma unroll 8
        for (int jj = 0; jj < H_DIM; jj++) s += shclf[tid * 65 + jj];
        out[ofs + tid] = s;
    }
}

extern "C" void kernel_launch(void* const* d_in, const int* in_sizes, int n_in,
                              void* d_out, int out_size)
{
    const float* x     = (const float*)d_in[0];
    const float* w_ih  = (const float*)d_in[1];
    const float* w_hh  = (const float*)d_in[2];
    const float* b_ih  = (const float*)d_in[3];
    const float* b_hh  = (const float*)d_in[4];
    const float* w_clf = (const float*)d_in[5];
    const float* b_clf = (const float*)d_in[6];
    float* out = (float*)d_out;

    cudaFuncSetAttribute(lstm_hmma_kernel,
                         cudaFuncAttributeMaxDynamicSharedMemorySize, SMEM_BYTES);
    lstm_hmma_kernel<<<NCTA, NTHR, SMEM_BYTES>>>(
        x, w_ih, w_hh, b_ih, b_hh, w_clf, b_clf, out);
}